// round 10
// baseline (speedup 1.0000x reference)
#include <cuda_runtime.h>
#include <cuda_bf16.h>

#define N_NODES 100000
#define N_EDGES 3200000
#define DIM 64
#define N_LAYERS 3
#define OUT_DIM (4 * DIM)

#define SCAN_B 1024
#define SCAN_NBLK ((N_NODES + SCAN_B - 1) / SCAN_B)   // 98
#define SPAD 68
#define NTILES ((N_NODES + 63) / 64)                   // 1563
#define GRID_PERSIST 296                               // 2 blocks per SM

// ---------------------------------------------------------------------------
// Scratch (allocation-free contract: __device__ globals)
// ---------------------------------------------------------------------------
__device__ int  g_count[N_NODES];            // per-dst degree histogram
__device__ int  g_cursor[N_NODES];           // running cursors for reorder
__device__ int  g_rowptr[N_NODES + 1];       // CSR offsets (dst-sorted)
__device__ int  g_blocksums[128];            // scan block sums
__device__ int2 g_sorted[N_EDGES];           // packed {src, a_bits}, dst-sorted
__device__ int  g_tile_counter[N_LAYERS];    // per-layer dynamic tile counters

// ---------------------------------------------------------------------------
// Generic zero (float4-vectorized, grid-stride)
// ---------------------------------------------------------------------------
__global__ void zero_kernel(float4* __restrict__ p, int n4) {
    int i = blockIdx.x * blockDim.x + threadIdx.x;
    const float4 z = make_float4(0.f, 0.f, 0.f, 0.f);
    for (; i < n4; i += gridDim.x * blockDim.x) p[i] = z;
}

__global__ void init_counters_kernel() {
    if (threadIdx.x < N_LAYERS) g_tile_counter[threadIdx.x] = 0;
}

// ---------------------------------------------------------------------------
// Copy x into out[:, 0:64]
// ---------------------------------------------------------------------------
__global__ void copy_x_kernel(const float4* __restrict__ x4, float4* __restrict__ out4) {
    int i = blockIdx.x * blockDim.x + threadIdx.x;
    if (i >= N_NODES * (DIM / 4)) return;
    int n = i >> 4;
    int c = i & 15;
    out4[n * (OUT_DIM / 4) + c] = x4[i];
}

// ---------------------------------------------------------------------------
// Counting sort by dst (one-time)
// ---------------------------------------------------------------------------
__global__ void hist_kernel(const int* __restrict__ dst) {
    int e = blockIdx.x * blockDim.x + threadIdx.x;
    if (e >= N_EDGES) return;
    atomicAdd(&g_count[dst[e]], 1);
}

__global__ __launch_bounds__(SCAN_B)
void scan_sum_kernel() {
    int i = blockIdx.x * SCAN_B + threadIdx.x;
    int v = (i < N_NODES) ? g_count[i] : 0;
    int lane = threadIdx.x & 31, w = threadIdx.x >> 5;
    #pragma unroll
    for (int d = 16; d; d >>= 1) v += __shfl_down_sync(~0u, v, d);
    __shared__ int s[32];
    if (lane == 0) s[w] = v;
    __syncthreads();
    if (w == 0) {
        v = s[lane];
        #pragma unroll
        for (int d = 16; d; d >>= 1) v += __shfl_down_sync(~0u, v, d);
        if (lane == 0) g_blocksums[blockIdx.x] = v;
    }
}

__global__ void scan_tops_kernel() {
    __shared__ int s[128];
    int tid = threadIdx.x;
    int v = (tid < SCAN_NBLK) ? g_blocksums[tid] : 0;
    s[tid] = v;
    __syncthreads();
    for (int off = 1; off < 128; off <<= 1) {
        int t = (tid >= off) ? s[tid - off] : 0;
        __syncthreads();
        s[tid] += t;
        __syncthreads();
    }
    if (tid < SCAN_NBLK) g_blocksums[tid] = s[tid] - v;   // exclusive
    if (tid == 0) g_rowptr[N_NODES] = N_EDGES;
}

__global__ __launch_bounds__(SCAN_B)
void scan_write_kernel() {
    int i = blockIdx.x * SCAN_B + threadIdx.x;
    int v = (i < N_NODES) ? g_count[i] : 0;
    int lane = threadIdx.x & 31, w = threadIdx.x >> 5;
    int inc = v;
    #pragma unroll
    for (int d = 1; d < 32; d <<= 1) {
        int t = __shfl_up_sync(~0u, inc, d);
        if (lane >= d) inc += t;
    }
    __shared__ int ws[32];
    if (lane == 31) ws[w] = inc;
    __syncthreads();
    if (w == 0) {
        int t = ws[lane];
        #pragma unroll
        for (int d = 1; d < 32; d <<= 1) {
            int u = __shfl_up_sync(~0u, t, d);
            if (lane >= d) t += u;
        }
        ws[lane] = t;
    }
    __syncthreads();
    int warpOff = (w == 0) ? 0 : ws[w - 1];
    int excl = inc - v + warpOff + g_blocksums[blockIdx.x];
    if (i < N_NODES) { g_cursor[i] = excl; g_rowptr[i] = excl; }
}

__global__ void reorder_kernel(const int* __restrict__ src,
                               const int* __restrict__ dst,
                               const float* __restrict__ a) {
    int e = blockIdx.x * blockDim.x + threadIdx.x;
    if (e >= N_EDGES) return;
    int d = dst[e];
    int pos = atomicAdd(&g_cursor[d], 1);
    int2 rec;
    rec.x = src[e];
    rec.y = __float_as_int(a[e]);
    g_sorted[pos] = rec;
}

// ---------------------------------------------------------------------------
// Fused layer kernel — producer/consumer warp specialization.
//   512 threads: warps 0-7 gather (R4 loop, 16 half-warps x 4 nodes) into a
//   double-buffered transposed s/p staging; warps 8-15 run R4's register-
//   tiled dual GEMM on the previous tile. Tiles claimed from a per-layer
//   global atomic counter (persistent grid, 2 blocks/SM).
// ---------------------------------------------------------------------------
__device__ __forceinline__ float lrelu(float v) {
    return v > 0.f ? v : 0.01f * v;
}

extern __shared__ float dyn_smem[];

__global__ __launch_bounds__(512, 2)
void fused_layer_kernel(const float4* __restrict__ hin, int strideF4,
                        const float* __restrict__ W1, const float* __restrict__ b1,
                        const float* __restrict__ W2, const float* __restrict__ b2,
                        float* __restrict__ outSeg, int layer) {
    float* sW1 = dyn_smem;                          // [4096]
    float* sW2 = sW1 + DIM * DIM;                   // [4096]
    float* sS  = sW2 + DIM * DIM;                   // [2][64*SPAD]
    float* sP  = sS + 2 * DIM * SPAD;               // [2][64*SPAD]
    __shared__ int sTileId[2];

    int t = threadIdx.x;

    // Weights -> shared (1024 float4 each; 512 threads -> 2 iters)
    {
        const float4* w1v = (const float4*)W1;
        const float4* w2v = (const float4*)W2;
        float4* s1v = (float4*)sW1;
        float4* s2v = (float4*)sW2;
        #pragma unroll
        for (int i = 0; i < 2; i++) {
            s1v[t + i * 512] = w1v[t + i * 512];
            s2v[t + i * 512] = w2v[t + i * 512];
        }
    }
    if (t == 0) {
        sTileId[0] = atomicAdd(&g_tile_counter[layer], 1);
        sTileId[1] = atomicAdd(&g_tile_counter[layer], 1);
    }
    __syncthreads();

    const bool producer = t < 256;
    int hw = t >> 4;            // producer half-warp 0..15
    int lane = t & 15;
    int k0 = lane * 4;
    int tc = t - 256;           // consumer thread id 0..255

    int consTile = -1;

    for (int iter = 0; ; iter++) {
        int buf = iter & 1;
        int prodTile = sTileId[buf];

        if (producer) {
            if (prodTile < NTILES) {
                float* bS = sS + buf * (DIM * SPAD);
                float* bP = sP + buf * (DIM * SPAD);
                int base = prodTile * 64;
                #pragma unroll
                for (int i = 0; i < 4; i++) {
                    int nloc = hw * 4 + i;
                    int node = base + nloc;
                    float4 acc = make_float4(0.f, 0.f, 0.f, 0.f);
                    float4 hv  = make_float4(0.f, 0.f, 0.f, 0.f);
                    if (node < N_NODES) {
                        int e  = g_rowptr[node];
                        int e1 = g_rowptr[node + 1];
                        for (; e + 1 < e1; e += 2) {
                            int2 r0 = g_sorted[e];
                            int2 r1 = g_sorted[e + 1];
                            float4 v0 = hin[(size_t)r0.x * strideF4 + lane];
                            float4 v1 = hin[(size_t)r1.x * strideF4 + lane];
                            float a0 = __int_as_float(r0.y);
                            float a1 = __int_as_float(r1.y);
                            acc.x = fmaf(a0, v0.x, acc.x);
                            acc.y = fmaf(a0, v0.y, acc.y);
                            acc.z = fmaf(a0, v0.z, acc.z);
                            acc.w = fmaf(a0, v0.w, acc.w);
                            acc.x = fmaf(a1, v1.x, acc.x);
                            acc.y = fmaf(a1, v1.y, acc.y);
                            acc.z = fmaf(a1, v1.z, acc.z);
                            acc.w = fmaf(a1, v1.w, acc.w);
                        }
                        if (e < e1) {
                            int2 r0 = g_sorted[e];
                            float4 v0 = hin[(size_t)r0.x * strideF4 + lane];
                            float a0 = __int_as_float(r0.y);
                            acc.x = fmaf(a0, v0.x, acc.x);
                            acc.y = fmaf(a0, v0.y, acc.y);
                            acc.z = fmaf(a0, v0.z, acc.z);
                            acc.w = fmaf(a0, v0.w, acc.w);
                        }
                        hv = hin[(size_t)node * strideF4 + lane];
                    }
                    bS[(k0 + 0) * SPAD + nloc] = hv.x + acc.x;
                    bS[(k0 + 1) * SPAD + nloc] = hv.y + acc.y;
                    bS[(k0 + 2) * SPAD + nloc] = hv.z + acc.z;
                    bS[(k0 + 3) * SPAD + nloc] = hv.w + acc.w;
                    bP[(k0 + 0) * SPAD + nloc] = hv.x * acc.x;
                    bP[(k0 + 1) * SPAD + nloc] = hv.y * acc.y;
                    bP[(k0 + 2) * SPAD + nloc] = hv.z * acc.z;
                    bP[(k0 + 3) * SPAD + nloc] = hv.w * acc.w;
                }
            }
        } else if (consTile >= 0) {
            float* bS = sS + (buf ^ 1) * (DIM * SPAD);
            float* bP = sP + (buf ^ 1) * (DIM * SPAD);
            int base = consTile * 64;
            int m0 = (tc & 15) * 4;
            int c0 = (tc >> 4) * 4;

            float acc1[4][4];
            float acc2[4][4];
            #pragma unroll
            for (int i = 0; i < 4; i++)
                #pragma unroll
                for (int j = 0; j < 4; j++) { acc1[i][j] = 0.f; acc2[i][j] = 0.f; }

            #pragma unroll 4
            for (int k = 0; k < DIM; k++) {
                float4 sv = *(const float4*)(bS + k * SPAD + m0);
                float4 pv = *(const float4*)(bP + k * SPAD + m0);
                float4 w1 = *(const float4*)(sW1 + k * DIM + c0);
                float4 w2 = *(const float4*)(sW2 + k * DIM + c0);
                float sm[4] = {sv.x, sv.y, sv.z, sv.w};
                float pm[4] = {pv.x, pv.y, pv.z, pv.w};
                float w1a[4] = {w1.x, w1.y, w1.z, w1.w};
                float w2a[4] = {w2.x, w2.y, w2.z, w2.w};
                #pragma unroll
                for (int i = 0; i < 4; i++) {
                    #pragma unroll
                    for (int j = 0; j < 4; j++) {
                        acc1[i][j] = fmaf(sm[i], w1a[j], acc1[i][j]);
                        acc2[i][j] = fmaf(pm[i], w2a[j], acc2[i][j]);
                    }
                }
            }

            float4 rb1 = *(const float4*)(b1 + c0);
            float4 rb2 = *(const float4*)(b2 + c0);
            float b1a[4] = {rb1.x, rb1.y, rb1.z, rb1.w};
            float b2a[4] = {rb2.x, rb2.y, rb2.z, rb2.w};

            #pragma unroll
            for (int i = 0; i < 4; i++) {
                int node = base + m0 + i;
                if (node >= N_NODES) break;
                float4 r;
                float* rp = (float*)&r;
                #pragma unroll
                for (int j = 0; j < 4; j++)
                    rp[j] = lrelu(acc1[i][j] + b1a[j]) + lrelu(acc2[i][j] + b2a[j]);
                *(float4*)(outSeg + (size_t)node * OUT_DIM + c0) = r;
            }
        }

        __syncthreads();
        consTile = prodTile;
        if (t == 0) sTileId[buf] = atomicAdd(&g_tile_counter[layer], 1);
        if (prodTile >= NTILES) break;   // consumer just handled the last tile
    }
}

// ---------------------------------------------------------------------------
// Launch
// ---------------------------------------------------------------------------
extern "C" void kernel_launch(void* const* d_in, const int* in_sizes, int n_in,
                              void* d_out, int out_size) {
    const float* x   = (const float*)d_in[0];
    const float* a   = (const float*)d_in[1];
    const float* W1s = (const float*)d_in[2];
    const float* b1s = (const float*)d_in[3];
    const float* W2s = (const float*)d_in[4];
    const float* b2s = (const float*)d_in[5];
    const int*   src = (const int*)d_in[6];
    const int*   dst = (const int*)d_in[7];
    float* out = (float*)d_out;

    int* cnt;
    cudaGetSymbolAddress((void**)&cnt, g_count);

    const int UPD_SMEM = (2 * DIM * DIM + 4 * DIM * SPAD) * (int)sizeof(float); // 102400
    cudaFuncSetAttribute(fused_layer_kernel, cudaFuncAttributeMaxDynamicSharedMemorySize, UPD_SMEM);

    // counters + out[:, 0:64] = x
    init_counters_kernel<<<1, 32>>>();
    {
        int n4 = N_NODES * (DIM / 4);
        copy_x_kernel<<<(n4 + 255) / 256, 256>>>((const float4*)x, (float4*)out);
    }

    // ---- One-time counting sort of edges by dst (CSR + packed records) ----
    zero_kernel<<<128, 256>>>((float4*)cnt, N_NODES / 4);
    hist_kernel<<<(N_EDGES + 255) / 256, 256>>>(dst);
    scan_sum_kernel<<<SCAN_NBLK, SCAN_B>>>();
    scan_tops_kernel<<<1, 128>>>();
    scan_write_kernel<<<SCAN_NBLK, SCAN_B>>>();
    reorder_kernel<<<(N_EDGES + 255) / 256, 256>>>(src, dst, a);

    // ---- Layers: fused producer/consumer, h read in-place from out ----
    for (int l = 0; l < N_LAYERS; l++) {
        const float4* hin;
        int strideF4;
        if (l == 0) { hin = (const float4*)x; strideF4 = DIM / 4; }
        else        { hin = (const float4*)out + (size_t)l * (DIM / 4); strideF4 = OUT_DIM / 4; }
        fused_layer_kernel<<<GRID_PERSIST, 512, UPD_SMEM>>>(
            hin, strideF4,
            W1s + (size_t)l * DIM * DIM, b1s + (size_t)l * DIM,
            W2s + (size_t)l * DIM * DIM, b2s + (size_t)l * DIM,
            out + (size_t)(l + 1) * DIM, l);
    }
}

// round 11
// speedup vs baseline: 1.0620x; 1.0620x over previous
#include <cuda_runtime.h>
#include <cuda_bf16.h>

#define N_NODES 100000
#define N_EDGES 3200000
#define DIM 64
#define N_LAYERS 3
#define OUT_DIM (4 * DIM)

#define SCAN_B 1024
#define SCAN_NBLK ((N_NODES + SCAN_B - 1) / SCAN_B)   // 98
#define SPAD 68

// Packed f32x2 helpers (sm_103a FFMA2 — only reachable via PTX)
#define PACK_F32X2(out, f) \
    asm("mov.b64 %0, {%1, %1};" : "=l"(out) : "r"(__float_as_uint(f)))
#define FMA_F32X2(d, a, b, c) \
    asm("fma.rn.f32x2 %0, %1, %2, %3;" : "=l"(d) : "l"(a), "l"(b), "l"(c))
#define UNPACK_F32X2(lo, hi, in) \
    asm("mov.b64 {%0, %1}, %2;" : "=r"(lo), "=r"(hi) : "l"(in))

// ---------------------------------------------------------------------------
// Scratch (allocation-free contract: __device__ globals)
// ---------------------------------------------------------------------------
__device__ int  g_count[N_NODES];            // per-dst degree histogram
__device__ int  g_cursor[N_NODES];           // running cursors for reorder
__device__ int  g_rowptr[N_NODES + 1];       // CSR offsets (dst-sorted)
__device__ int  g_blocksums[128];            // scan block sums
__device__ int2 g_sorted[N_EDGES];           // packed {src, a_bits}, dst-sorted

// ---------------------------------------------------------------------------
// Generic zero (float4-vectorized, grid-stride)
// ---------------------------------------------------------------------------
__global__ void zero_kernel(float4* __restrict__ p, int n4) {
    int i = blockIdx.x * blockDim.x + threadIdx.x;
    const float4 z = make_float4(0.f, 0.f, 0.f, 0.f);
    for (; i < n4; i += gridDim.x * blockDim.x) p[i] = z;
}

// ---------------------------------------------------------------------------
// Copy x into out[:, 0:64]
// ---------------------------------------------------------------------------
__global__ void copy_x_kernel(const float4* __restrict__ x4, float4* __restrict__ out4) {
    int i = blockIdx.x * blockDim.x + threadIdx.x;
    if (i >= N_NODES * (DIM / 4)) return;
    int n = i >> 4;
    int c = i & 15;
    out4[n * (OUT_DIM / 4) + c] = x4[i];
}

// ---------------------------------------------------------------------------
// Counting sort by dst (one-time)
// ---------------------------------------------------------------------------
__global__ void hist_kernel(const int* __restrict__ dst) {
    int e = blockIdx.x * blockDim.x + threadIdx.x;
    if (e >= N_EDGES) return;
    atomicAdd(&g_count[dst[e]], 1);
}

__global__ __launch_bounds__(SCAN_B)
void scan_sum_kernel() {
    int i = blockIdx.x * SCAN_B + threadIdx.x;
    int v = (i < N_NODES) ? g_count[i] : 0;
    int lane = threadIdx.x & 31, w = threadIdx.x >> 5;
    #pragma unroll
    for (int d = 16; d; d >>= 1) v += __shfl_down_sync(~0u, v, d);
    __shared__ int s[32];
    if (lane == 0) s[w] = v;
    __syncthreads();
    if (w == 0) {
        v = s[lane];
        #pragma unroll
        for (int d = 16; d; d >>= 1) v += __shfl_down_sync(~0u, v, d);
        if (lane == 0) g_blocksums[blockIdx.x] = v;
    }
}

__global__ void scan_tops_kernel() {
    __shared__ int s[128];
    int tid = threadIdx.x;
    int v = (tid < SCAN_NBLK) ? g_blocksums[tid] : 0;
    s[tid] = v;
    __syncthreads();
    for (int off = 1; off < 128; off <<= 1) {
        int t = (tid >= off) ? s[tid - off] : 0;
        __syncthreads();
        s[tid] += t;
        __syncthreads();
    }
    if (tid < SCAN_NBLK) g_blocksums[tid] = s[tid] - v;   // exclusive
    if (tid == 0) g_rowptr[N_NODES] = N_EDGES;
}

__global__ __launch_bounds__(SCAN_B)
void scan_write_kernel() {
    int i = blockIdx.x * SCAN_B + threadIdx.x;
    int v = (i < N_NODES) ? g_count[i] : 0;
    int lane = threadIdx.x & 31, w = threadIdx.x >> 5;
    int inc = v;
    #pragma unroll
    for (int d = 1; d < 32; d <<= 1) {
        int t = __shfl_up_sync(~0u, inc, d);
        if (lane >= d) inc += t;
    }
    __shared__ int ws[32];
    if (lane == 31) ws[w] = inc;
    __syncthreads();
    if (w == 0) {
        int t = ws[lane];
        #pragma unroll
        for (int d = 1; d < 32; d <<= 1) {
            int u = __shfl_up_sync(~0u, t, d);
            if (lane >= d) t += u;
        }
        ws[lane] = t;
    }
    __syncthreads();
    int warpOff = (w == 0) ? 0 : ws[w - 1];
    int excl = inc - v + warpOff + g_blocksums[blockIdx.x];
    if (i < N_NODES) { g_cursor[i] = excl; g_rowptr[i] = excl; }
}

__global__ void reorder_kernel(const int* __restrict__ src,
                               const int* __restrict__ dst,
                               const float* __restrict__ a) {
    int e = blockIdx.x * blockDim.x + threadIdx.x;
    if (e >= N_EDGES) return;
    int d = dst[e];
    int pos = atomicAdd(&g_cursor[d], 1);
    int2 rec;
    rec.x = src[e];
    rec.y = __float_as_int(a[e]);
    g_sorted[pos] = rec;
}

// ---------------------------------------------------------------------------
// Fused layer kernel (R4 structure; GEMM inner loop in packed f32x2):
//   per block: own 64 dst nodes; 16 half-warps each gather+accumulate 4
//   nodes' edge segments (register h_n, unroll-2), stage s/p transposed in
//   shared, then register-tiled dual GEMM (FFMA2) + bias + lrelu + sum.
// ---------------------------------------------------------------------------
__device__ __forceinline__ float lrelu(float v) {
    return v > 0.f ? v : 0.01f * v;
}

extern __shared__ float dyn_smem[];

__global__ __launch_bounds__(256)
void fused_layer_kernel(const float4* __restrict__ hin, int strideF4,
                        const float* __restrict__ W1, const float* __restrict__ b1,
                        const float* __restrict__ W2, const float* __restrict__ b2,
                        float* __restrict__ outSeg) {
    float* sW1 = dyn_smem;                 // [64*64]
    float* sW2 = sW1 + DIM * DIM;          // [64*64]
    float* sS  = sW2 + DIM * DIM;          // [64][SPAD] k-major
    float* sP  = sS + DIM * SPAD;          // [64][SPAD]

    int t = threadIdx.x;

    // Weights -> shared
    {
        const float4* w1v = (const float4*)W1;
        const float4* w2v = (const float4*)W2;
        float4* s1v = (float4*)sW1;
        float4* s2v = (float4*)sW2;
        #pragma unroll
        for (int i = 0; i < 4; i++) {
            s1v[t + i * 256] = w1v[t + i * 256];
            s2v[t + i * 256] = w2v[t + i * 256];
        }
    }

    int base = blockIdx.x * 64;
    int hw = t >> 4;        // half-warp id 0..15
    int lane = t & 15;      // float4-column within a 64-float row
    int k0 = lane * 4;

    // Gather + accumulate + stage. Each half-warp owns 4 consecutive nodes.
    #pragma unroll
    for (int i = 0; i < 4; i++) {
        int nloc = hw * 4 + i;
        int node = base + nloc;
        float4 acc = make_float4(0.f, 0.f, 0.f, 0.f);
        float4 hv  = make_float4(0.f, 0.f, 0.f, 0.f);
        if (node < N_NODES) {
            int e  = g_rowptr[node];
            int e1 = g_rowptr[node + 1];
            // unrolled by 2: two independent gathers in flight
            for (; e + 1 < e1; e += 2) {
                int2 r0 = g_sorted[e];
                int2 r1 = g_sorted[e + 1];
                float4 v0 = hin[(size_t)r0.x * strideF4 + lane];
                float4 v1 = hin[(size_t)r1.x * strideF4 + lane];
                float a0 = __int_as_float(r0.y);
                float a1 = __int_as_float(r1.y);
                acc.x = fmaf(a0, v0.x, acc.x);
                acc.y = fmaf(a0, v0.y, acc.y);
                acc.z = fmaf(a0, v0.z, acc.z);
                acc.w = fmaf(a0, v0.w, acc.w);
                acc.x = fmaf(a1, v1.x, acc.x);
                acc.y = fmaf(a1, v1.y, acc.y);
                acc.z = fmaf(a1, v1.z, acc.z);
                acc.w = fmaf(a1, v1.w, acc.w);
            }
            if (e < e1) {
                int2 r0 = g_sorted[e];
                float4 v0 = hin[(size_t)r0.x * strideF4 + lane];
                float a0 = __int_as_float(r0.y);
                acc.x = fmaf(a0, v0.x, acc.x);
                acc.y = fmaf(a0, v0.y, acc.y);
                acc.z = fmaf(a0, v0.z, acc.z);
                acc.w = fmaf(a0, v0.w, acc.w);
            }
            hv = hin[(size_t)node * strideF4 + lane];
        }
        // stage s = h + hn, p = h * hn, transposed [k][node]
        sS[(k0 + 0) * SPAD + nloc] = hv.x + acc.x;
        sS[(k0 + 1) * SPAD + nloc] = hv.y + acc.y;
        sS[(k0 + 2) * SPAD + nloc] = hv.z + acc.z;
        sS[(k0 + 3) * SPAD + nloc] = hv.w + acc.w;
        sP[(k0 + 0) * SPAD + nloc] = hv.x * acc.x;
        sP[(k0 + 1) * SPAD + nloc] = hv.y * acc.y;
        sP[(k0 + 2) * SPAD + nloc] = hv.z * acc.z;
        sP[(k0 + 3) * SPAD + nloc] = hv.w * acc.w;
    }
    __syncthreads();

    // Register-tiled dual GEMM, packed f32x2: 4 nodes x 4 cols per thread.
    // acc1[i][jp] holds cols {c0+2jp, c0+2jp+1} for node m0+i.
    int m0 = (t & 15) * 4;
    int c0 = (t >> 4) * 4;

    unsigned long long acc1[4][2];
    unsigned long long acc2[4][2];
    #pragma unroll
    for (int i = 0; i < 4; i++)
        #pragma unroll
        for (int j = 0; j < 2; j++) { acc1[i][j] = 0ull; acc2[i][j] = 0ull; }

    #pragma unroll 4
    for (int k = 0; k < DIM; k++) {
        float4 sv = *(const float4*)(sS + k * SPAD + m0);
        float4 pv = *(const float4*)(sP + k * SPAD + m0);
        ulonglong2 w1p = *(const ulonglong2*)(sW1 + k * DIM + c0);
        ulonglong2 w2p = *(const ulonglong2*)(sW2 + k * DIM + c0);
        float sm[4] = {sv.x, sv.y, sv.z, sv.w};
        float pm[4] = {pv.x, pv.y, pv.z, pv.w};
        #pragma unroll
        for (int i = 0; i < 4; i++) {
            unsigned long long smp, pmp;
            PACK_F32X2(smp, sm[i]);
            PACK_F32X2(pmp, pm[i]);
            FMA_F32X2(acc1[i][0], smp, w1p.x, acc1[i][0]);
            FMA_F32X2(acc1[i][1], smp, w1p.y, acc1[i][1]);
            FMA_F32X2(acc2[i][0], pmp, w2p.x, acc2[i][0]);
            FMA_F32X2(acc2[i][1], pmp, w2p.y, acc2[i][1]);
        }
    }

    float4 rb1 = *(const float4*)(b1 + c0);
    float4 rb2 = *(const float4*)(b2 + c0);
    float b1a[4] = {rb1.x, rb1.y, rb1.z, rb1.w};
    float b2a[4] = {rb2.x, rb2.y, rb2.z, rb2.w};

    #pragma unroll
    for (int i = 0; i < 4; i++) {
        int node = base + m0 + i;
        if (node >= N_NODES) break;
        unsigned int u0, u1;
        float a1[4], a2[4];
        UNPACK_F32X2(u0, u1, acc1[i][0]); a1[0] = __uint_as_float(u0); a1[1] = __uint_as_float(u1);
        UNPACK_F32X2(u0, u1, acc1[i][1]); a1[2] = __uint_as_float(u0); a1[3] = __uint_as_float(u1);
        UNPACK_F32X2(u0, u1, acc2[i][0]); a2[0] = __uint_as_float(u0); a2[1] = __uint_as_float(u1);
        UNPACK_F32X2(u0, u1, acc2[i][1]); a2[2] = __uint_as_float(u0); a2[3] = __uint_as_float(u1);
        float4 r;
        float* rp = (float*)&r;
        #pragma unroll
        for (int j = 0; j < 4; j++)
            rp[j] = lrelu(a1[j] + b1a[j]) + lrelu(a2[j] + b2a[j]);
        *(float4*)(outSeg + (size_t)node * OUT_DIM + c0) = r;
    }
}

// ---------------------------------------------------------------------------
// Launch
// ---------------------------------------------------------------------------
extern "C" void kernel_launch(void* const* d_in, const int* in_sizes, int n_in,
                              void* d_out, int out_size) {
    const float* x   = (const float*)d_in[0];
    const float* a   = (const float*)d_in[1];
    const float* W1s = (const float*)d_in[2];
    const float* b1s = (const float*)d_in[3];
    const float* W2s = (const float*)d_in[4];
    const float* b2s = (const float*)d_in[5];
    const int*   src = (const int*)d_in[6];
    const int*   dst = (const int*)d_in[7];
    float* out = (float*)d_out;

    int* cnt;
    cudaGetSymbolAddress((void**)&cnt, g_count);

    const int UPD_SMEM = (2 * DIM * DIM + 2 * DIM * SPAD) * (int)sizeof(float); // 67584
    cudaFuncSetAttribute(fused_layer_kernel, cudaFuncAttributeMaxDynamicSharedMemorySize, UPD_SMEM);

    // out[:, 0:64] = x
    {
        int n4 = N_NODES * (DIM / 4);
        copy_x_kernel<<<(n4 + 255) / 256, 256>>>((const float4*)x, (float4*)out);
    }

    // ---- One-time counting sort of edges by dst (CSR + packed records) ----
    zero_kernel<<<128, 256>>>((float4*)cnt, N_NODES / 4);
    hist_kernel<<<(N_EDGES + 255) / 256, 256>>>(dst);
    scan_sum_kernel<<<SCAN_NBLK, SCAN_B>>>();
    scan_tops_kernel<<<1, 128>>>();
    scan_write_kernel<<<SCAN_NBLK, SCAN_B>>>();
    reorder_kernel<<<(N_EDGES + 255) / 256, 256>>>(src, dst, a);

    // ---- Layers: fully fused, h read in-place from output tensor ----
    int grid = (N_NODES + 63) / 64;
    for (int l = 0; l < N_LAYERS; l++) {
        const float4* hin;
        int strideF4;
        if (l == 0) { hin = (const float4*)x; strideF4 = DIM / 4; }
        else        { hin = (const float4*)out + (size_t)l * (DIM / 4); strideF4 = OUT_DIM / 4; }
        fused_layer_kernel<<<grid, 256, UPD_SMEM>>>(
            hin, strideF4,
            W1s + (size_t)l * DIM * DIM, b1s + (size_t)l * DIM,
            W2s + (size_t)l * DIM * DIM, b2s + (size_t)l * DIM,
            out + (size_t)(l + 1) * DIM);
    }
}

// round 12
// speedup vs baseline: 1.0958x; 1.0318x over previous
#include <cuda_runtime.h>
#include <cuda_bf16.h>

#define N_NODES 100000
#define N_EDGES 3200000
#define DIM 64
#define N_LAYERS 3
#define OUT_DIM (4 * DIM)

#define SCAN_B 1024
#define SCAN_NBLK ((N_NODES + SCAN_B - 1) / SCAN_B)   // 98
#define SPAD 68
#define NTILES ((N_NODES + 63) / 64)                   // 1563
#define GRID_PERSIST 296                               // 2 blocks per SM
#define PROD_T 384                                     // 12 producer warps
#define N_PHW 24                                       // producer half-warps

// ---------------------------------------------------------------------------
// Scratch (allocation-free contract: __device__ globals)
// ---------------------------------------------------------------------------
__device__ int  g_count[N_NODES];            // per-dst degree histogram
__device__ int  g_cursor[N_NODES];           // running cursors for reorder
__device__ int  g_rowptr[N_NODES + 1];       // CSR offsets (dst-sorted)
__device__ int  g_blocksums[128];            // scan block sums
__device__ int2 g_sorted[N_EDGES];           // packed {src, a_bits}, dst-sorted
__device__ int  g_tile_counter[N_LAYERS];    // per-layer dynamic tile counters

// ---------------------------------------------------------------------------
// Generic zero (float4-vectorized, grid-stride)
// ---------------------------------------------------------------------------
__global__ void zero_kernel(float4* __restrict__ p, int n4) {
    int i = blockIdx.x * blockDim.x + threadIdx.x;
    const float4 z = make_float4(0.f, 0.f, 0.f, 0.f);
    for (; i < n4; i += gridDim.x * blockDim.x) p[i] = z;
}

__global__ void init_counters_kernel() {
    if (threadIdx.x < N_LAYERS) g_tile_counter[threadIdx.x] = 0;
}

// ---------------------------------------------------------------------------
// Copy x into out[:, 0:64]
// ---------------------------------------------------------------------------
__global__ void copy_x_kernel(const float4* __restrict__ x4, float4* __restrict__ out4) {
    int i = blockIdx.x * blockDim.x + threadIdx.x;
    if (i >= N_NODES * (DIM / 4)) return;
    int n = i >> 4;
    int c = i & 15;
    out4[n * (OUT_DIM / 4) + c] = x4[i];
}

// ---------------------------------------------------------------------------
// Counting sort by dst (one-time)
// ---------------------------------------------------------------------------
__global__ void hist_kernel(const int* __restrict__ dst) {
    int e = blockIdx.x * blockDim.x + threadIdx.x;
    if (e >= N_EDGES) return;
    atomicAdd(&g_count[dst[e]], 1);
}

__global__ __launch_bounds__(SCAN_B)
void scan_sum_kernel() {
    int i = blockIdx.x * SCAN_B + threadIdx.x;
    int v = (i < N_NODES) ? g_count[i] : 0;
    int lane = threadIdx.x & 31, w = threadIdx.x >> 5;
    #pragma unroll
    for (int d = 16; d; d >>= 1) v += __shfl_down_sync(~0u, v, d);
    __shared__ int s[32];
    if (lane == 0) s[w] = v;
    __syncthreads();
    if (w == 0) {
        v = s[lane];
        #pragma unroll
        for (int d = 16; d; d >>= 1) v += __shfl_down_sync(~0u, v, d);
        if (lane == 0) g_blocksums[blockIdx.x] = v;
    }
}

__global__ void scan_tops_kernel() {
    __shared__ int s[128];
    int tid = threadIdx.x;
    int v = (tid < SCAN_NBLK) ? g_blocksums[tid] : 0;
    s[tid] = v;
    __syncthreads();
    for (int off = 1; off < 128; off <<= 1) {
        int t = (tid >= off) ? s[tid - off] : 0;
        __syncthreads();
        s[tid] += t;
        __syncthreads();
    }
    if (tid < SCAN_NBLK) g_blocksums[tid] = s[tid] - v;   // exclusive
    if (tid == 0) g_rowptr[N_NODES] = N_EDGES;
}

__global__ __launch_bounds__(SCAN_B)
void scan_write_kernel() {
    int i = blockIdx.x * SCAN_B + threadIdx.x;
    int v = (i < N_NODES) ? g_count[i] : 0;
    int lane = threadIdx.x & 31, w = threadIdx.x >> 5;
    int inc = v;
    #pragma unroll
    for (int d = 1; d < 32; d <<= 1) {
        int t = __shfl_up_sync(~0u, inc, d);
        if (lane >= d) inc += t;
    }
    __shared__ int ws[32];
    if (lane == 31) ws[w] = inc;
    __syncthreads();
    if (w == 0) {
        int t = ws[lane];
        #pragma unroll
        for (int d = 1; d < 32; d <<= 1) {
            int u = __shfl_up_sync(~0u, t, d);
            if (lane >= d) t += u;
        }
        ws[lane] = t;
    }
    __syncthreads();
    int warpOff = (w == 0) ? 0 : ws[w - 1];
    int excl = inc - v + warpOff + g_blocksums[blockIdx.x];
    if (i < N_NODES) { g_cursor[i] = excl; g_rowptr[i] = excl; }
}

__global__ void reorder_kernel(const int* __restrict__ src,
                               const int* __restrict__ dst,
                               const float* __restrict__ a) {
    int e = blockIdx.x * blockDim.x + threadIdx.x;
    if (e >= N_EDGES) return;
    int d = dst[e];
    int pos = atomicAdd(&g_cursor[d], 1);
    int2 rec;
    rec.x = src[e];
    rec.y = __float_as_int(a[e]);
    g_sorted[pos] = rec;
}

// ---------------------------------------------------------------------------
// Fused layer kernel — ASYMMETRIC producer/consumer warp specialization.
//   512 threads: warps 0-11 (384 thr, 24 half-warps) gather into a
//   double-buffered transposed s/p staging (R4's unroll-2 gather loop);
//   warps 12-15 (128 thr) run the register-tiled dual GEMM on the previous
//   tile in two column passes. Tiles claimed from a per-layer global atomic
//   counter (persistent grid, 2 blocks/SM).
// ---------------------------------------------------------------------------
__device__ __forceinline__ float lrelu(float v) {
    return v > 0.f ? v : 0.01f * v;
}

extern __shared__ float dyn_smem[];

__global__ __launch_bounds__(512, 2)
void fused_layer_kernel(const float4* __restrict__ hin, int strideF4,
                        const float* __restrict__ W1, const float* __restrict__ b1,
                        const float* __restrict__ W2, const float* __restrict__ b2,
                        float* __restrict__ outSeg, int layer) {
    float* sW1 = dyn_smem;                          // [4096]
    float* sW2 = sW1 + DIM * DIM;                   // [4096]
    float* sS  = sW2 + DIM * DIM;                   // [2][64*SPAD]
    float* sP  = sS + 2 * DIM * SPAD;               // [2][64*SPAD]
    __shared__ int sTileId[2];

    int t = threadIdx.x;

    // Weights -> shared (1024 float4 each; 512 threads -> 2 iters)
    {
        const float4* w1v = (const float4*)W1;
        const float4* w2v = (const float4*)W2;
        float4* s1v = (float4*)sW1;
        float4* s2v = (float4*)sW2;
        #pragma unroll
        for (int i = 0; i < 2; i++) {
            s1v[t + i * 512] = w1v[t + i * 512];
            s2v[t + i * 512] = w2v[t + i * 512];
        }
    }
    if (t == 0) {
        sTileId[0] = atomicAdd(&g_tile_counter[layer], 1);
        sTileId[1] = atomicAdd(&g_tile_counter[layer], 1);
    }
    __syncthreads();

    const bool producer = t < PROD_T;
    int hw = t >> 4;            // producer half-warp 0..23
    int lane = t & 15;
    int k0 = lane * 4;
    int tc = t - PROD_T;        // consumer thread id 0..127

    int consTile = -1;

    for (int iter = 0; ; iter++) {
        int buf = iter & 1;
        int prodTile = sTileId[buf];

        if (producer) {
            if (prodTile < NTILES) {
                float* bS = sS + buf * (DIM * SPAD);
                float* bP = sP + buf * (DIM * SPAD);
                int base = prodTile * 64;
                // 24 half-warps cover 64 nodes: nloc = hw, hw+24, hw+48
                #pragma unroll
                for (int i = 0; i < 3; i++) {
                    int nloc = hw + N_PHW * i;
                    if (nloc >= 64) break;
                    int node = base + nloc;
                    float4 acc = make_float4(0.f, 0.f, 0.f, 0.f);
                    float4 hv  = make_float4(0.f, 0.f, 0.f, 0.f);
                    if (node < N_NODES) {
                        int e  = g_rowptr[node];
                        int e1 = g_rowptr[node + 1];
                        for (; e + 1 < e1; e += 2) {
                            int2 r0 = g_sorted[e];
                            int2 r1 = g_sorted[e + 1];
                            float4 v0 = hin[(size_t)r0.x * strideF4 + lane];
                            float4 v1 = hin[(size_t)r1.x * strideF4 + lane];
                            float a0 = __int_as_float(r0.y);
                            float a1 = __int_as_float(r1.y);
                            acc.x = fmaf(a0, v0.x, acc.x);
                            acc.y = fmaf(a0, v0.y, acc.y);
                            acc.z = fmaf(a0, v0.z, acc.z);
                            acc.w = fmaf(a0, v0.w, acc.w);
                            acc.x = fmaf(a1, v1.x, acc.x);
                            acc.y = fmaf(a1, v1.y, acc.y);
                            acc.z = fmaf(a1, v1.z, acc.z);
                            acc.w = fmaf(a1, v1.w, acc.w);
                        }
                        if (e < e1) {
                            int2 r0 = g_sorted[e];
                            float4 v0 = hin[(size_t)r0.x * strideF4 + lane];
                            float a0 = __int_as_float(r0.y);
                            acc.x = fmaf(a0, v0.x, acc.x);
                            acc.y = fmaf(a0, v0.y, acc.y);
                            acc.z = fmaf(a0, v0.z, acc.z);
                            acc.w = fmaf(a0, v0.w, acc.w);
                        }
                        hv = hin[(size_t)node * strideF4 + lane];
                    }
                    bS[(k0 + 0) * SPAD + nloc] = hv.x + acc.x;
                    bS[(k0 + 1) * SPAD + nloc] = hv.y + acc.y;
                    bS[(k0 + 2) * SPAD + nloc] = hv.z + acc.z;
                    bS[(k0 + 3) * SPAD + nloc] = hv.w + acc.w;
                    bP[(k0 + 0) * SPAD + nloc] = hv.x * acc.x;
                    bP[(k0 + 1) * SPAD + nloc] = hv.y * acc.y;
                    bP[(k0 + 2) * SPAD + nloc] = hv.z * acc.z;
                    bP[(k0 + 3) * SPAD + nloc] = hv.w * acc.w;
                }
            }
        } else if (consTile >= 0) {
            float* bS = sS + (buf ^ 1) * (DIM * SPAD);
            float* bP = sP + (buf ^ 1) * (DIM * SPAD);
            int base = consTile * 64;
            int m0 = (tc & 15) * 4;

            // Two column passes: c0 and c0+32
            #pragma unroll
            for (int pass = 0; pass < 2; pass++) {
                int c0 = (tc >> 4) * 4 + pass * 32;

                float acc1[4][4];
                float acc2[4][4];
                #pragma unroll
                for (int i = 0; i < 4; i++)
                    #pragma unroll
                    for (int j = 0; j < 4; j++) { acc1[i][j] = 0.f; acc2[i][j] = 0.f; }

                #pragma unroll 4
                for (int k = 0; k < DIM; k++) {
                    float4 sv = *(const float4*)(bS + k * SPAD + m0);
                    float4 pv = *(const float4*)(bP + k * SPAD + m0);
                    float4 w1 = *(const float4*)(sW1 + k * DIM + c0);
                    float4 w2 = *(const float4*)(sW2 + k * DIM + c0);
                    float sm[4] = {sv.x, sv.y, sv.z, sv.w};
                    float pm[4] = {pv.x, pv.y, pv.z, pv.w};
                    float w1a[4] = {w1.x, w1.y, w1.z, w1.w};
                    float w2a[4] = {w2.x, w2.y, w2.z, w2.w};
                    #pragma unroll
                    for (int i = 0; i < 4; i++) {
                        #pragma unroll
                        for (int j = 0; j < 4; j++) {
                            acc1[i][j] = fmaf(sm[i], w1a[j], acc1[i][j]);
                            acc2[i][j] = fmaf(pm[i], w2a[j], acc2[i][j]);
                        }
                    }
                }

                float4 rb1 = *(const float4*)(b1 + c0);
                float4 rb2 = *(const float4*)(b2 + c0);
                float b1a[4] = {rb1.x, rb1.y, rb1.z, rb1.w};
                float b2a[4] = {rb2.x, rb2.y, rb2.z, rb2.w};

                #pragma unroll
                for (int i = 0; i < 4; i++) {
                    int node = base + m0 + i;
                    if (node >= N_NODES) break;
                    float4 r;
                    float* rp = (float*)&r;
                    #pragma unroll
                    for (int j = 0; j < 4; j++)
                        rp[j] = lrelu(acc1[i][j] + b1a[j]) + lrelu(acc2[i][j] + b2a[j]);
                    *(float4*)(outSeg + (size_t)node * OUT_DIM + c0) = r;
                }
            }
        }

        __syncthreads();
        consTile = prodTile;
        if (t == 0) sTileId[buf] = atomicAdd(&g_tile_counter[layer], 1);
        if (prodTile >= NTILES) break;   // consumer just handled the last tile
    }
}

// ---------------------------------------------------------------------------
// Launch
// ---------------------------------------------------------------------------
extern "C" void kernel_launch(void* const* d_in, const int* in_sizes, int n_in,
                              void* d_out, int out_size) {
    const float* x   = (const float*)d_in[0];
    const float* a   = (const float*)d_in[1];
    const float* W1s = (const float*)d_in[2];
    const float* b1s = (const float*)d_in[3];
    const float* W2s = (const float*)d_in[4];
    const float* b2s = (const float*)d_in[5];
    const int*   src = (const int*)d_in[6];
    const int*   dst = (const int*)d_in[7];
    float* out = (float*)d_out;

    int* cnt;
    cudaGetSymbolAddress((void**)&cnt, g_count);

    const int UPD_SMEM = (2 * DIM * DIM + 4 * DIM * SPAD) * (int)sizeof(float); // 102400
    cudaFuncSetAttribute(fused_layer_kernel, cudaFuncAttributeMaxDynamicSharedMemorySize, UPD_SMEM);

    // counters + out[:, 0:64] = x
    init_counters_kernel<<<1, 32>>>();
    {
        int n4 = N_NODES * (DIM / 4);
        copy_x_kernel<<<(n4 + 255) / 256, 256>>>((const float4*)x, (float4*)out);
    }

    // ---- One-time counting sort of edges by dst (CSR + packed records) ----
    zero_kernel<<<128, 256>>>((float4*)cnt, N_NODES / 4);
    hist_kernel<<<(N_EDGES + 255) / 256, 256>>>(dst);
    scan_sum_kernel<<<SCAN_NBLK, SCAN_B>>>();
    scan_tops_kernel<<<1, 128>>>();
    scan_write_kernel<<<SCAN_NBLK, SCAN_B>>>();
    reorder_kernel<<<(N_EDGES + 255) / 256, 256>>>(src, dst, a);

    // ---- Layers: fused producer/consumer, h read in-place from out ----
    for (int l = 0; l < N_LAYERS; l++) {
        const float4* hin;
        int strideF4;
        if (l == 0) { hin = (const float4*)x; strideF4 = DIM / 4; }
        else        { hin = (const float4*)out + (size_t)l * (DIM / 4); strideF4 = OUT_DIM / 4; }
        fused_layer_kernel<<<GRID_PERSIST, 512, UPD_SMEM>>>(
            hin, strideF4,
            W1s + (size_t)l * DIM * DIM, b1s + (size_t)l * DIM,
            W2s + (size_t)l * DIM * DIM, b2s + (size_t)l * DIM,
            out + (size_t)(l + 1) * DIM, l);
    }
}